// round 12
// baseline (speedup 1.0000x reference)
#include <cuda_runtime.h>
#include <cstdint>
#include <math.h>

#define NTOK 8192
#define CDIM 64
#define NEXP 16
#define CAP  640
#define NEC  ((size_t)NTOK * NEXP * CAP)       /* 83,886,080 elements */
#define SCALAR_OFF (2 * NEC)                   /* z, aux, std */
#define LOGITS_OFF (2 * NEC + 3)

#define TOK_BYTES (CDIM * 64 * 4)              /* 16384 bytes per token */
#define TOK_PER_BLK 8

// ---------------- scratch (no allocs allowed) ----------------
__device__ float              g_probs[NTOK * NEXP];
__device__ float              g_lse2[NTOK];
__device__ unsigned long long g_keys[NTOK];
__device__ int                g_expert[NTOK];
__device__ int                g_bcnt[NEXP];
__device__ unsigned long long g_bkeys[NEXP * NTOK];   // per-expert key buckets (1MB)

// ---------------- mbarrier / TMA helpers ----------------
__device__ __forceinline__ uint32_t smem_u32(const void* p) {
    return (uint32_t)__cvta_generic_to_shared(p);
}
__device__ __forceinline__ void mbar_init(uint32_t mbar, uint32_t cnt) {
    asm volatile("mbarrier.init.shared.b64 [%0], %1;" :: "r"(mbar), "r"(cnt) : "memory");
}
__device__ __forceinline__ void mbar_expect_tx(uint32_t mbar, uint32_t bytes) {
    asm volatile("mbarrier.arrive.expect_tx.shared.b64 _, [%0], %1;"
                 :: "r"(mbar), "r"(bytes) : "memory");
}
__device__ __forceinline__ void bulk_ld(uint32_t dst_smem, const void* gsrc,
                                        uint32_t bytes, uint32_t mbar) {
    asm volatile("cp.async.bulk.shared::cluster.global.mbarrier::complete_tx::bytes "
                 "[%0], [%1], %2, [%3];"
                 :: "r"(dst_smem), "l"(gsrc), "r"(bytes), "r"(mbar) : "memory");
}
__device__ __forceinline__ void mbar_wait(uint32_t mbar, uint32_t parity) {
    asm volatile(
        "{\n\t"
        ".reg .pred P;\n\t"
        "WAIT_%=:\n\t"
        "mbarrier.try_wait.parity.shared::cta.b64 P, [%0], %1;\n\t"
        "@P bra DONE_%=;\n\t"
        "bra WAIT_%=;\n\t"
        "DONE_%=:\n\t"
        "}"
        :: "r"(mbar), "r"(parity) : "memory");
}

// ---------------- kernel 1: TMA-pipelined pool + gate + softmax + buckets ----
// 1024 blocks x 128 threads; each block streams 8 tokens through a
// double-buffered 16KB smem tile (TMA for j+1 issued before waiting on j).
__global__ void __launch_bounds__(128) gating_kernel(const float* __restrict__ X,
                              const float* __restrict__ Wg,
                              const float* __restrict__ bg,
                              float* __restrict__ out_logits) {
    __shared__ __align__(128) float buf[2][CDIM * 64];   // 2 x 16KB
    __shared__ __align__(8)  unsigned long long mbar_store[2];
    __shared__ float pooled[CDIM];
    const int t = threadIdx.x;
    const int w = t >> 5, l = t & 31;
    const int n0 = blockIdx.x * TOK_PER_BLK;

    const uint32_t mb0 = smem_u32(&mbar_store[0]);
    const uint32_t mb1 = smem_u32(&mbar_store[1]);
    if (t == 0) { mbar_init(mb0, 1); mbar_init(mb1, 1); }
    __syncthreads();

    // prologue: stage token 0
    if (t == 0) {
        mbar_expect_tx(mb0, TOK_BYTES);
        bulk_ld(smem_u32(&buf[0][0]), X + (size_t)n0 * (CDIM * 64), TOK_BYTES, mb0);
    }

#pragma unroll 1
    for (int j = 0; j < TOK_PER_BLK; j++) {
        const int cur = j & 1;
        // issue next token's TMA before waiting on current (overlap)
        if (t == 0 && j + 1 < TOK_PER_BLK) {
            const uint32_t mbn = (j + 1) & 1 ? mb1 : mb0;
            mbar_expect_tx(mbn, TOK_BYTES);
            bulk_ld(smem_u32(&buf[(j + 1) & 1][0]),
                    X + (size_t)(n0 + j + 1) * (CDIM * 64), TOK_BYTES, mbn);
        }
        mbar_wait(cur ? mb1 : mb0, (j >> 1) & 1);

        const int n = n0 + j;
        // pooling from smem: warp w owns channels [16w,16w+16);
        // lane reads f4 idx = w*256 + i*32 + l; channel = w*16 + 2i + (l>>4)
        const float4* bp = (const float4*)&buf[cur][0] + w * 256;
        float s[8];
#pragma unroll
        for (int i = 0; i < 8; i++) {
            float4 v = bp[i * 32 + l];
            s[i] = (v.x + v.y) + (v.z + v.w);
        }
#pragma unroll
        for (int i = 0; i < 8; i++) {
            float r = s[i];
            r += __shfl_xor_sync(0xffffffffu, r, 8);
            r += __shfl_xor_sync(0xffffffffu, r, 4);
            r += __shfl_xor_sync(0xffffffffu, r, 2);
            r += __shfl_xor_sync(0xffffffffu, r, 1);
            if (l == 0)  pooled[w * 16 + 2 * i]     = r * (1.f / 64.f);
            if (l == 16) pooled[w * 16 + 2 * i + 1] = r * (1.f / 64.f);
        }
        __syncthreads();   // pooled complete; all buf[cur] reads retired

        if (t < 32) {  // warp 0: gate + softmax/argmax; lanes 0..15 = experts
            float lgt = -3.0e38f;
            if (l < NEXP) {
                float d = bg[l];
#pragma unroll
                for (int k = 0; k < CDIM; k++) d += pooled[k] * Wg[k * NEXP + l];
                float v = d * (1.f / 1.5f);
                lgt = fminf(10.f, fmaxf(-10.f, v));
                out_logits[(size_t)n * NEXP + l] = lgt;
            }
            float m = lgt;
            int   mi = l & 15;
#pragma unroll
            for (int o = 8; o; o >>= 1) {
                float om = __shfl_xor_sync(0xffffffffu, m, o);
                int   oi = __shfl_xor_sync(0xffffffffu, mi, o);
                if (om > m || (om == m && oi < mi)) { m = om; mi = oi; }
            }
            float ev = (l < NEXP) ? expf(lgt - m) : 0.f;
            float sum = ev;
#pragma unroll
            for (int o = 8; o; o >>= 1) sum += __shfl_xor_sync(0xffffffffu, sum, o);
            if (l < NEXP) g_probs[n * NEXP + l] = ev / sum;
            if (l == 0) {
                float lse = m + logf(sum);
                g_lse2[n] = lse * lse;
                float pe = 1.f / sum;  // top-1 prob = exp(0)/sum
                g_expert[n] = mi;
                // key: expert (4b) | prob bits (monotonic) | 8191-n (stable tie-break)
                unsigned long long key = ((unsigned long long)mi << 45)
                                       | ((unsigned long long)__float_as_uint(pe) << 13)
                                       | (unsigned long long)(8191 - n);
                g_keys[n] = key;
                int slot = atomicAdd(&g_bcnt[mi], 1);
                g_bkeys[mi * NTOK + slot] = key;
            }
        }
        __syncthreads();   // protect pooled from next iteration's writers
    }
}

// ---------------- kernel 2: fused rank + write-out ----------------
// One block per token: scan own expert's bucket (L2-resident) for rank,
// then emit the token's dispatch & combine slabs (zeros + one hot element).
__global__ void __launch_bounds__(256) writeout_kernel(float* __restrict__ out) {
    __shared__ int s_warp[8];
    __shared__ int s_pos;
    const int n = blockIdx.x;
    const int t = threadIdx.x;

    const unsigned long long mykey = g_keys[n];
    const int e = g_expert[n];
    const int m = g_bcnt[e];
    const unsigned long long* bk = g_bkeys + (size_t)e * NTOK;
    int cnt = 0;
    for (int j = t; j < m; j += 256) cnt += (int)(bk[j] > mykey);
#pragma unroll
    for (int o = 16; o; o >>= 1) cnt += __shfl_xor_sync(0xffffffffu, cnt, o);
    if ((t & 31) == 0) s_warp[t >> 5] = cnt;
    __syncthreads();
    if (t == 0) {
        int p = 0;
#pragma unroll
        for (int w = 0; w < 8; w++) p += s_warp[w];
        s_pos = p;
    }
    __syncthreads();
    const int pos = s_pos;

    const int hot = (pos < CAP) ? (e * CAP + pos) : -1;
    const int hot_v = hot >> 2;
    const int hot_e = hot & 3;

    float4* dsp = (float4*)(out + (size_t)n * (NEXP * CAP));
    float4* cmb = (float4*)(out + NEC + (size_t)n * (NEXP * CAP));

    const float4 z = make_float4(0.f, 0.f, 0.f, 0.f);
#pragma unroll
    for (int i = 0; i < 10; i++) {
        int idx = t + i * 256;
        float4 v = z;
        if (hot >= 0 && idx == hot_v) ((float*)&v)[hot_e] = 1.f;
        __stcs(&dsp[idx], v);   // streaming (evict-first) stores
        __stcs(&cmb[idx], v);   // combine == dispatch for top-1 routing
    }
}

// ---------------- kernel 3: scalar losses (latency-bound; overlapped) -------
__global__ void finalize_kernel(const float* __restrict__ logits,
                                float* __restrict__ scal) {
    __shared__ float part[1024];
    __shared__ float cs[NEXP];
    __shared__ float res_z, res_s1, res_s2;
    int t = threadIdx.x;

    float cp = 0.f;
    for (int i = t; i < NTOK * NEXP; i += 1024) cp += g_probs[i];
    part[t] = cp;
    __syncthreads();
    if (t < NEXP) {
        float s = 0.f;
        for (int k = t; k < 1024; k += NEXP) s += part[k];
        cs[t] = s;
    }
    __syncthreads();

    float sz = 0.f;
    for (int i = t; i < NTOK; i += 1024) sz += g_lse2[i];
    part[t] = sz;
    __syncthreads();
    for (int o = 512; o; o >>= 1) { if (t < o) part[t] += part[t + o]; __syncthreads(); }
    if (t == 0) res_z = part[0];
    __syncthreads();

    float s1 = 0.f, s2 = 0.f;
    for (int i = t; i < NTOK * NEXP; i += 1024) {
        float v = logits[i];
        s1 += v; s2 += v * v;
    }
    part[t] = s1;
    __syncthreads();
    for (int o = 512; o; o >>= 1) { if (t < o) part[t] += part[t + o]; __syncthreads(); }
    if (t == 0) res_s1 = part[0];
    __syncthreads();
    part[t] = s2;
    __syncthreads();
    for (int o = 512; o; o >>= 1) { if (t < o) part[t] += part[t + o]; __syncthreads(); }
    if (t == 0) res_s2 = part[0];
    __syncthreads();

    if (t == 0) {
        scal[0] = res_z / (float)NTOK;  // z_loss
        float aux = 0.f;
        for (int e = 0; e < NEXP; e++) {
            int surv = g_bcnt[e] < CAP ? g_bcnt[e] : CAP;  // surviving tokens
            aux += ((float)surv / (float)NTOK) * (cs[e] / (float)NTOK);
        }
        scal[1] = aux * (float)NEXP;    // aux_loss
        float inv = 1.f / (float)(NTOK * NEXP);
        float mean = res_s1 * inv;
        float var = res_s2 * inv - mean * mean;
        scal[2] = sqrtf(fmaxf(var, 0.f));  // logits_std
    }
}

// ---------------- launch ----------------
extern "C" void kernel_launch(void* const* d_in, const int* in_sizes, int n_in,
                              void* d_out, int out_size) {
    const float* X  = (const float*)d_in[0];
    const float* Wg = (const float*)d_in[1];
    const float* bg = (const float*)d_in[2];
    float* out = (float*)d_out;

    static cudaStream_t s_side = nullptr;
    static cudaEvent_t  ev_gate = nullptr, ev_fin = nullptr;
    static void* bcnt_addr = nullptr;
    if (s_side == nullptr) {
        cudaStreamCreateWithFlags(&s_side, cudaStreamNonBlocking);
        cudaEventCreateWithFlags(&ev_gate, cudaEventDisableTiming);
        cudaEventCreateWithFlags(&ev_fin,  cudaEventDisableTiming);
        cudaGetSymbolAddress(&bcnt_addr, g_bcnt);
    }

    // Phase 1 (pure read): TMA-pipelined gating
    cudaMemsetAsync(bcnt_addr, 0, NEXP * sizeof(int), 0);
    gating_kernel<<<NTOK / TOK_PER_BLK, 128>>>(X, Wg, bg, out + LOGITS_OFF);
    cudaEventRecord(ev_gate, 0);

    // Latency-bound scalar losses fork after gating (hidden under write phase)
    cudaStreamWaitEvent(s_side, ev_gate, 0);
    finalize_kernel<<<1, 1024, 0, s_side>>>(out + LOGITS_OFF, out + SCALAR_OFF);
    cudaEventRecord(ev_fin, s_side);

    // Phase 2 (pure write): fused rank + zero-fill + one-hot, 672MB
    writeout_kernel<<<NTOK, 256>>>(out);

    cudaStreamWaitEvent(0, ev_fin, 0);
}

// round 13
// speedup vs baseline: 1.1062x; 1.1062x over previous
#include <cuda_runtime.h>
#include <cstdint>
#include <math.h>

#define NTOK 8192
#define CDIM 64
#define NEXP 16
#define CAP  640
#define NEC  ((size_t)NTOK * NEXP * CAP)       /* 83,886,080 elements */
#define SCALAR_OFF (2 * NEC)                   /* z, aux, std */
#define LOGITS_OFF (2 * NEC + 3)

// ---------------- scratch (no allocs allowed) ----------------
__device__ float              g_probs[NTOK * NEXP];
__device__ float              g_lse2[NTOK];
__device__ unsigned long long g_keys[NTOK];
__device__ int                g_expert[NTOK];
__device__ int                g_bcnt[NEXP];
__device__ unsigned long long g_bkeys[NEXP * NTOK];   // per-expert key buckets (1MB)

// ---------------- kernel 1: pool + gate + softmax + bucket scatter ----------
// one block (64 threads) per token; 256-bit loads (LDG.E.256) halve the LSU
// issue count vs float4 — the read phase was issue-bound at ~1 LDG/cyc/SM.
__global__ void gating_kernel(const float* __restrict__ X,
                              const float* __restrict__ Wg,
                              const float* __restrict__ bg,
                              float* __restrict__ out_logits) {
    __shared__ float part[64 * 9];    // [channel][slot 0..7], stride 9 (coprime 32)
    __shared__ float pooled[CDIM];
    __shared__ float lg[NEXP];
    const int n = blockIdx.x;
    const int t = threadIdx.x;  // 0..63

    // Each iter: 64 threads x 32B = 2KB contiguous. Thread sums its 8 floats,
    // which lie inside one channel: channel = i*8 + (t>>3), slot = t&7.
    const float* xp = X + (size_t)n * (CDIM * 64);
#pragma unroll
    for (int i = 0; i < 8; i++) {
        const float* p = xp + i * 512 + t * 8;
        float a0, a1, a2, a3, a4, a5, a6, a7;
        asm volatile("ld.global.nc.v8.f32 {%0,%1,%2,%3,%4,%5,%6,%7}, [%8];"
                     : "=f"(a0), "=f"(a1), "=f"(a2), "=f"(a3),
                       "=f"(a4), "=f"(a5), "=f"(a6), "=f"(a7)
                     : "l"(p));
        part[(i * 8 + (t >> 3)) * 9 + (t & 7)] =
            ((a0 + a1) + (a2 + a3)) + ((a4 + a5) + (a6 + a7));
    }
    __syncthreads();

    float s = 0.f;
#pragma unroll
    for (int j = 0; j < 8; j++) s += part[t * 9 + j];
    pooled[t] = s * (1.f / 64.f);
    __syncthreads();

    if (t < NEXP) {
        float d = bg[t];
#pragma unroll
        for (int k = 0; k < CDIM; k++) d += pooled[k] * Wg[k * NEXP + t];
        float l = d * (1.f / 1.5f);
        l = fminf(10.f, fmaxf(-10.f, l));
        lg[t] = l;
        out_logits[(size_t)n * NEXP + t] = l;
    }
    __syncthreads();

    if (t < 32) {  // warp 0: softmax/argmax; lanes 0..15 carry data
        float v = (t < 16) ? lg[t] : -3.0e38f;
        float m = v;
        int   mi = t;
#pragma unroll
        for (int o = 8; o; o >>= 1) {
            float om = __shfl_xor_sync(0xffffffffu, m, o);
            int   oi = __shfl_xor_sync(0xffffffffu, mi, o);
            if (om > m || (om == m && oi < mi)) { m = om; mi = oi; }
        }
        float ev = (t < 16) ? expf(v - m) : 0.f;
        float sum = ev;
#pragma unroll
        for (int o = 8; o; o >>= 1) sum += __shfl_xor_sync(0xffffffffu, sum, o);
        if (t < 16) g_probs[n * NEXP + t] = ev / sum;
        if (t == 0) {
            float lse = m + logf(sum);
            g_lse2[n] = lse * lse;
            float pe = 1.f / sum;  // top-1 prob = exp(0)/sum
            g_expert[n] = mi;
            // key: expert (4b) | prob bits (monotonic, positive floats) | 8191-n (stable tie-break)
            unsigned long long key = ((unsigned long long)mi << 45)
                                   | ((unsigned long long)__float_as_uint(pe) << 13)
                                   | (unsigned long long)(8191 - n);
            g_keys[n] = key;
            // bucket scatter (order in bucket irrelevant: rank recomputed by compares)
            int slot = atomicAdd(&g_bcnt[mi], 1);
            g_bkeys[mi * NTOK + slot] = key;
        }
    }
}

// ---------------- kernel 2: fused rank + write-out ----------------
// One block per token: scan own expert's bucket (L2-resident) for rank,
// then emit the token's dispatch & combine slabs (zeros + one hot element).
__global__ void __launch_bounds__(256) writeout_kernel(float* __restrict__ out) {
    __shared__ int s_warp[8];
    __shared__ int s_pos;
    const int n = blockIdx.x;
    const int t = threadIdx.x;

    const unsigned long long mykey = g_keys[n];
    const int e = g_expert[n];
    const int m = g_bcnt[e];
    const unsigned long long* bk = g_bkeys + (size_t)e * NTOK;
    int cnt = 0;
    for (int j = t; j < m; j += 256) cnt += (int)(bk[j] > mykey);
#pragma unroll
    for (int o = 16; o; o >>= 1) cnt += __shfl_xor_sync(0xffffffffu, cnt, o);
    if ((t & 31) == 0) s_warp[t >> 5] = cnt;
    __syncthreads();
    if (t == 0) {
        int p = 0;
#pragma unroll
        for (int w = 0; w < 8; w++) p += s_warp[w];
        s_pos = p;
    }
    __syncthreads();
    const int pos = s_pos;

    const int hot = (pos < CAP) ? (e * CAP + pos) : -1;
    const int hot_v = hot >> 2;
    const int hot_e = hot & 3;

    float4* dsp = (float4*)(out + (size_t)n * (NEXP * CAP));
    float4* cmb = (float4*)(out + NEC + (size_t)n * (NEXP * CAP));

    const float4 z = make_float4(0.f, 0.f, 0.f, 0.f);
#pragma unroll
    for (int i = 0; i < 10; i++) {
        int idx = t + i * 256;
        float4 v = z;
        if (hot >= 0 && idx == hot_v) ((float*)&v)[hot_e] = 1.f;
        __stcs(&dsp[idx], v);   // streaming (evict-first) stores
        __stcs(&cmb[idx], v);   // combine == dispatch for top-1 routing
    }
}

// ---------------- kernel 3: scalar losses (latency-bound; overlapped) -------
__global__ void finalize_kernel(const float* __restrict__ logits,
                                float* __restrict__ scal) {
    __shared__ float part[1024];
    __shared__ float cs[NEXP];
    __shared__ float res_z, res_s1, res_s2;
    int t = threadIdx.x;

    // per-expert prob column sums: thread t only touches column t&15
    float cp = 0.f;
    for (int i = t; i < NTOK * NEXP; i += 1024) cp += g_probs[i];
    part[t] = cp;
    __syncthreads();
    if (t < NEXP) {
        float s = 0.f;
        for (int k = t; k < 1024; k += NEXP) s += part[k];
        cs[t] = s;
    }
    __syncthreads();

    float sz = 0.f;
    for (int i = t; i < NTOK; i += 1024) sz += g_lse2[i];
    part[t] = sz;
    __syncthreads();
    for (int o = 512; o; o >>= 1) { if (t < o) part[t] += part[t + o]; __syncthreads(); }
    if (t == 0) res_z = part[0];
    __syncthreads();

    float s1 = 0.f, s2 = 0.f;
    for (int i = t; i < NTOK * NEXP; i += 1024) {
        float v = logits[i];
        s1 += v; s2 += v * v;
    }
    part[t] = s1;
    __syncthreads();
    for (int o = 512; o; o >>= 1) { if (t < o) part[t] += part[t + o]; __syncthreads(); }
    if (t == 0) res_s1 = part[0];
    __syncthreads();
    part[t] = s2;
    __syncthreads();
    for (int o = 512; o; o >>= 1) { if (t < o) part[t] += part[t + o]; __syncthreads(); }
    if (t == 0) res_s2 = part[0];
    __syncthreads();

    if (t == 0) {
        scal[0] = res_z / (float)NTOK;  // z_loss
        float aux = 0.f;
        for (int e = 0; e < NEXP; e++) {
            int surv = g_bcnt[e] < CAP ? g_bcnt[e] : CAP;  // surviving tokens
            aux += ((float)surv / (float)NTOK) * (cs[e] / (float)NTOK);
        }
        scal[1] = aux * (float)NEXP;    // aux_loss
        float inv = 1.f / (float)(NTOK * NEXP);
        float mean = res_s1 * inv;
        float var = res_s2 * inv - mean * mean;
        scal[2] = sqrtf(fmaxf(var, 0.f));  // logits_std
    }
}

// ---------------- launch ----------------
extern "C" void kernel_launch(void* const* d_in, const int* in_sizes, int n_in,
                              void* d_out, int out_size) {
    const float* X  = (const float*)d_in[0];
    const float* Wg = (const float*)d_in[1];
    const float* bg = (const float*)d_in[2];
    float* out = (float*)d_out;

    static cudaStream_t s_side = nullptr;
    static cudaEvent_t  ev_gate = nullptr, ev_fin = nullptr;
    static void* bcnt_addr = nullptr;
    if (s_side == nullptr) {
        cudaStreamCreateWithFlags(&s_side, cudaStreamNonBlocking);
        cudaEventCreateWithFlags(&ev_gate, cudaEventDisableTiming);
        cudaEventCreateWithFlags(&ev_fin,  cudaEventDisableTiming);
        cudaGetSymbolAddress(&bcnt_addr, g_bcnt);
    }

    // Phase 1 (pure read): zero counters (memset node), then gating
    cudaMemsetAsync(bcnt_addr, 0, NEXP * sizeof(int), 0);
    gating_kernel<<<NTOK, 64>>>(X, Wg, bg, out + LOGITS_OFF);
    cudaEventRecord(ev_gate, 0);

    // Latency-bound scalar losses fork after gating (hidden under write phase)
    cudaStreamWaitEvent(s_side, ev_gate, 0);
    finalize_kernel<<<1, 1024, 0, s_side>>>(out + LOGITS_OFF, out + SCALAR_OFF);
    cudaEventRecord(ev_fin, s_side);

    // Phase 2 (pure write): fused rank + zero-fill + one-hot, 672MB
    writeout_kernel<<<NTOK, 256>>>(out);

    cudaStreamWaitEvent(0, ev_fin, 0);
}